// round 1
// baseline (speedup 1.0000x reference)
#include <cuda_runtime.h>
#include <cuda_bf16.h>

// LinearRationalSpline forward.
// inputs:  [16384, 64] f32          (N = 1048576 elements)
// params:  [16384, 64, 63] f32      (w[16], h[16], d[15], lam[16] per element)
// out:     [2*N] f32  -> out[0:N] = outputs, out[N:2N] = logabsdet

#define TPB 128
#define NBINS 16

__device__ __forceinline__ float softplus_f(float v) {
    // stable: max(v,0) + log1p(exp(-|v|))
    return fmaxf(v, 0.0f) + __logf(1.0f + __expf(-fabsf(v)));
}

__global__ __launch_bounds__(TPB)
void lrs_kernel(const float* __restrict__ inputs,
                const float* __restrict__ params,
                float* __restrict__ out,
                int N)
{
    constexpr float BOUND = 3.0f;
    constexpr float MBW   = 0.001f;   // MIN_BIN_WIDTH
    constexpr float MBH   = 0.001f;   // MIN_BIN_HEIGHT
    constexpr float MIND  = 0.001f;   // MIN_DERIVATIVE
    constexpr float MINL  = 0.025f;   // MIN_LAMBDA
    constexpr float EPSV  = 1e-6f;

    __shared__ float sp[TPB * 63];

    const int tid = threadIdx.x;
    const long long blockElem = (long long)blockIdx.x * TPB;
    const int remaining = N - (int)blockElem;          // elements this block handles
    const int nElem = remaining < TPB ? remaining : TPB;

    // ---- stage params into shared (coalesced) ----
    {
        const long long fbase = blockElem * 63;        // float offset
        const int nFloats = nElem * 63;
        if (nElem == TPB) {
            // 128*63 floats = 2016 float4, base 16B-aligned (32256B per block)
            const float4* g4 = reinterpret_cast<const float4*>(params + fbase);
            float4* s4 = reinterpret_cast<float4*>(sp);
            #pragma unroll
            for (int i = 0; i < (TPB * 63) / 4 / TPB; i++)
                s4[i * TPB + tid] = g4[i * TPB + tid];
            // (TPB*63)/4 = 2016 = 15.75*128 -> handle the remainder 96
            {
                int i = ((TPB * 63) / 4 / TPB) * TPB + tid;   // 1920 + tid
                if (i < (TPB * 63) / 4) s4[i] = g4[i];
            }
        } else {
            for (int i = tid; i < nFloats; i += TPB)
                sp[i] = params[fbase + i];
        }
    }
    __syncthreads();

    const int e = (int)blockElem + tid;
    if (e >= N) return;

    const float x = inputs[e];
    const float* __restrict__ p = sp + tid * 63;   // stride 63 -> conflict-free

    // ---- widths softmax cumsum ----
    float wmax = p[0];
    #pragma unroll
    for (int i = 1; i < NBINS; i++) wmax = fmaxf(wmax, p[i]);
    float cw[NBINS];
    {
        float s = 0.0f;
        #pragma unroll
        for (int i = 0; i < NBINS; i++) { s += __expf(p[i] - wmax); cw[i] = s; }
    }
    const float Aw = 6.0f * (1.0f - 16.0f * MBW) * __frcp_rn(cw[NBINS - 1]);

    // ---- heights softmax cumsum ----
    float hmax = p[16];
    #pragma unroll
    for (int i = 1; i < NBINS; i++) hmax = fmaxf(hmax, p[16 + i]);
    float ch[NBINS];
    {
        float s = 0.0f;
        #pragma unroll
        for (int i = 0; i < NBINS; i++) { s += __expf(p[16 + i] - hmax); ch[i] = s; }
    }
    const float Ah = 6.0f * (1.0f - 16.0f * MBH) * __frcp_rn(ch[NBINS - 1]);

    // ---- width knots (kwv[i-1] = knot_i for i=1..16, knot_16 = BOUND exact) ----
    float kwv[NBINS];
    #pragma unroll
    for (int i = 1; i <= 15; i++)
        kwv[i - 1] = fmaf(Aw, cw[i - 1], 6.0f * MBW * (float)i - BOUND);
    kwv[15] = BOUND;

    // ---- bin search: count knots with knot_i + eps <= x ----
    int cnt = 0;
    float cumw = -BOUND;   // knot_b
    #pragma unroll
    for (int i = 1; i <= 16; i++) {
        bool c = (kwv[i - 1] + EPSV) <= x;
        cnt += c ? 1 : 0;
        if (i < 16 && c) cumw = kwv[i - 1];
    }
    float wnext = BOUND;   // knot_{b+1}
    #pragma unroll
    for (int i = 15; i >= 1; i--) {
        if (!((kwv[i - 1] + EPSV) <= x)) wnext = kwv[i - 1];
    }
    const int b = cnt > 15 ? 15 : cnt;

    const float input_widths = wnext - cumw;

    // ---- select cumexp-heights at b-1 and b (predicated register selects) ----
    float ch0 = 0.0f, ch1 = ch[0];
    #pragma unroll
    for (int i = 1; i < NBINS; i++) {
        bool g = (b >= i);
        ch0 = g ? ch[i - 1] : ch0;
        ch1 = g ? ch[i]     : ch1;
    }
    const float ya  = (b == 0)  ? -BOUND : fmaf(Ah, ch0, 6.0f * MBH * (float)b - BOUND);
    const float ykn = (b == 15) ?  BOUND : fmaf(Ah, ch1, 6.0f * MBH * (float)(b + 1) - BOUND);
    const float input_heights = ykn - ya;
    const float yb = input_heights + ya;

    // ---- derivatives at b, b+1 (only 2 softplus; edges are 1 - MIND) ----
    const float d0r = p[32 + (b > 0  ? b - 1 : 0)];
    const float d1r = p[32 + (b < 15 ? b     : 14)];
    const float d0 = (b == 0)  ? (1.0f - MIND) : (MIND + softplus_f(d0r));
    const float d1 = (b == 15) ? (1.0f - MIND) : (MIND + softplus_f(d1r));

    // ---- lambda (only 1 sigmoid) ----
    const float lraw = p[47 + b];
    const float sig = __frcp_rn(1.0f + __expf(-lraw));
    const float lam = fmaf(1.0f - 2.0f * MINL, sig, MINL);

    // ---- rational spline ----
    const float wbv = __fsqrt_rn(__fdividef(d0, d1));
    const float lwb = lam * wbv;
    const float delta = __fdividef(input_heights, input_widths);
    const float wc = __fdividef(fmaf(lam, d0, (wbv - lwb) * d1), delta);
    const float l1 = 1.0f - lam;
    const float yc = __fdividef(lwb * yb + l1 * ya, l1 + lwb);

    const float theta = __fdividef(x - cumw, input_widths);
    const bool ind = theta <= lam;
    const float ltheta = lam - theta;

    const float wcyc = wc * yc;
    const float wcyctheta = wcyc * theta;
    const float wbyb = wbv * yb;
    const float num = ind ? fmaf(ya, ltheta, wcyctheta)
                          : (wcyc - wcyctheta) - wbyb * ltheta;
    const float wctheta = wc * theta;
    const float den = ind ? (wctheta + ltheta)
                          : (wc - wctheta) - wbv * ltheta;
    const float outv = __fdividef(num, den);

    const float dnum = __fdividef(
        wc * (ind ? lam * (yc - ya) : (wbv - lwb) * (yb - yc)),
        input_widths);
    const float lad = __logf(dnum) - 2.0f * __logf(fabsf(den));

    const bool outside = (x < -BOUND) || (x > BOUND);
    out[e]     = outside ? x    : outv;
    out[N + e] = outside ? 0.0f : lad;
}

extern "C" void kernel_launch(void* const* d_in, const int* in_sizes, int n_in,
                              void* d_out, int out_size) {
    const float* inputs = (const float*)d_in[0];
    const float* params = (const float*)d_in[1];
    float* out = (float*)d_out;
    const int N = in_sizes[0];               // 1048576
    const int grid = (N + TPB - 1) / TPB;
    lrs_kernel<<<grid, TPB>>>(inputs, params, out, N);
}